// round 2
// baseline (speedup 1.0000x reference)
#include <cuda_runtime.h>
#include <cuda_bf16.h>
#include <math.h>

#define T_SEQ   512
#define GATES   500
#define HID     125
#define DHID    250      // 2*HID
#define MLPH    512
#define NN      512

// Scratch (device globals; no allocation allowed)
__device__ float g_A[2 * T_SEQ * GATES];   // input projections (fwd/bwd)
__device__ float g_H[T_SEQ * DHID];        // concat hidden states
__device__ float g_P[2 * NN * MLPH];       // Pa, Pb(+b1)

// ---------------------------------------------------------------------------
// helpers
// ---------------------------------------------------------------------------
__device__ __forceinline__ float2 ffma2(float2 a, float2 b, float2 c) {
    float2 d;
    asm("{\n\t"
        ".reg .b64 ra, rb, rc, rd;\n\t"
        "mov.b64 ra, {%2, %3};\n\t"
        "mov.b64 rb, {%4, %5};\n\t"
        "mov.b64 rc, {%6, %7};\n\t"
        "fma.rn.f32x2 rd, ra, rb, rc;\n\t"
        "mov.b64 {%0, %1}, rd;\n\t"
        "}"
        : "=f"(d.x), "=f"(d.y)
        : "f"(a.x), "f"(a.y), "f"(b.x), "f"(b.y), "f"(c.x), "f"(c.y));
    return d;
}

__device__ __forceinline__ float tanh_mufu(float x) {
    float y;
    asm("tanh.approx.f32 %0, %1;" : "=f"(y) : "f"(x));
    return y;
}

__device__ __forceinline__ float sig_acc(float x) {
    return __fdividef(1.0f, 1.0f + __expf(-x));
}
__device__ __forceinline__ float tanh_acc(float x) {
    return 1.0f - __fdividef(2.0f, 1.0f + __expf(2.0f * x));
}

// ---------------------------------------------------------------------------
// Generic tiled SGEMM:  C[m][n] = sum_k A[rowA(m)][k] * B[n][k] (+b1[n]+b2[n])
// rowA(m) = rev ? M-1-m : m.  32x32 tile, 256 threads, 2x2 per thread.
// ---------------------------------------------------------------------------
__global__ void __launch_bounds__(256) sgemm_tn(
    const float* __restrict__ A, int lda, int rev, int M,
    const float* __restrict__ B, int ldb, int N, int K,
    const float* __restrict__ bias1, const float* __restrict__ bias2,
    float* __restrict__ C, int ldc)
{
    __shared__ float As[16][34];
    __shared__ float Bs[16][34];

    const int tid = threadIdx.x;
    const int ti = tid & 15;          // m micro index (pair)
    const int tn = tid >> 4;          // n micro index (pair)
    const int m0 = blockIdx.x * 32;
    const int n0 = blockIdx.y * 32;

    float acc00 = 0.f, acc01 = 0.f, acc10 = 0.f, acc11 = 0.f;

    for (int kc = 0; kc < K; kc += 16) {
#pragma unroll
        for (int it = 0; it < 2; ++it) {
            int idx = tid + it * 256;
            int mm = idx >> 4, kk = idx & 15;
            int k = kc + kk;
            int m = m0 + mm;
            int ra = rev ? (M - 1 - m) : m;
            As[kk][mm] = (m < M && k < K) ? A[(long)ra * lda + k] : 0.f;
            int n = n0 + mm;
            Bs[kk][mm] = (n < N && k < K) ? B[(long)n * ldb + k] : 0.f;
        }
        __syncthreads();
#pragma unroll
        for (int kk = 0; kk < 16; ++kk) {
            float2 av = *(const float2*)&As[kk][2 * ti];
            float2 bv = *(const float2*)&Bs[kk][2 * tn];
            acc00 = fmaf(av.x, bv.x, acc00);
            acc01 = fmaf(av.x, bv.y, acc01);
            acc10 = fmaf(av.y, bv.x, acc10);
            acc11 = fmaf(av.y, bv.y, acc11);
        }
        __syncthreads();
    }

    int m_ = m0 + 2 * ti;
    int n_ = n0 + 2 * tn;
    float b0 = 0.f, b1v = 0.f;
    if (bias1) { if (n_ < N) b0 += bias1[n_]; if (n_ + 1 < N) b1v += bias1[n_ + 1]; }
    if (bias2) { if (n_ < N) b0 += bias2[n_]; if (n_ + 1 < N) b1v += bias2[n_ + 1]; }
    if (m_ < M) {
        if (n_ < N)     C[(long)m_ * ldc + n_]     = acc00 + b0;
        if (n_ + 1 < N) C[(long)m_ * ldc + n_ + 1] = acc01 + b1v;
    }
    if (m_ + 1 < M) {
        if (n_ < N)     C[(long)(m_ + 1) * ldc + n_]     = acc10 + b0;
        if (n_ + 1 < N) C[(long)(m_ + 1) * ldc + n_ + 1] = acc11 + b1v;
    }
}

// ---------------------------------------------------------------------------
// LSTM recurrence. grid = 2 (dir), block = 512.
// Thread r < 500 owns gate row r of Whh: cols 0..95 in registers (f32x2),
// cols 96..123 as float2 pairs in smem, col 124 scalar in smem.
// Dynamic smem layout (floats):
//   [0, 14000)      : 14 pairs * 500 rows float2  (cols 96..123)
//   [14000, 14500)  : col-124 weights
//   [14500, 15012)  : g scratch (500 used, padded to 512)
//   [15012, 15140)  : h (125 used, padded to 128; 16B aligned)
// ---------------------------------------------------------------------------
#define LSTM_SMEM_FLOATS (14 * 500 * 2 + 500 + 512 + 128)
#define LSTM_SMEM_BYTES  (LSTM_SMEM_FLOATS * 4)

__global__ void __launch_bounds__(512, 1) lstm_kernel(
    const float* __restrict__ Whh_f,
    const float* __restrict__ Whh_b,
    const float* __restrict__ A,     // [2][512][500]
    float* __restrict__ H)           // [512][250]
{
    extern __shared__ float smem[];
    float2* sh_w2 = (float2*)smem;             // 14*500 float2
    float*  sh_wl = smem + 14 * 500 * 2;       // 500
    float*  sh_g  = sh_wl + 500;               // 512
    float*  sh_h  = sh_g + 512;                // 128

    const int tid = threadIdx.x;
    const int dir = blockIdx.x;
    const float* __restrict__ Whh = dir ? Whh_b : Whh_f;
    const float* __restrict__ Ad = A + dir * (T_SEQ * GATES);
    const int r = tid;

    // stage shared weights: pairs for cols 96..123, scalar col 124
    for (int idx = tid; idx < 14 * 500; idx += 512) {
        int p = idx / 500, rr = idx - p * 500;
        sh_w2[p * 500 + rr] = make_float2(Whh[rr * 125 + 96 + 2 * p],
                                          Whh[rr * 125 + 96 + 2 * p + 1]);
    }
    for (int idx = tid; idx < 500; idx += 512)
        sh_wl[idx] = Whh[idx * 125 + 124];

    // register weights: cols 0..95
    float2 wreg[48];
    if (r < GATES) {
        const float* wr = Whh + r * 125;
#pragma unroll
        for (int p = 0; p < 48; ++p)
            wreg[p] = make_float2(wr[2 * p], wr[2 * p + 1]);
    }

    if (tid < 128) sh_h[tid] = 0.f;
    float creg = 0.f;
    float a_cur = (r < GATES) ? Ad[r] : 0.f;
    __syncthreads();

    for (int t = 0; t < T_SEQ; ++t) {
        float a_next = (r < GATES && t < T_SEQ - 1) ? Ad[(t + 1) * GATES + r] : 0.f;
        if (r < GATES) {
            float2 acc2a = make_float2(0.f, 0.f);
            float2 acc2b = make_float2(0.f, 0.f);
            const float4* h4 = (const float4*)sh_h;
#pragma unroll
            for (int p4 = 0; p4 < 24; ++p4) {      // cols 0..95 (registers)
                float4 hv = h4[p4];
                acc2a = ffma2(wreg[2 * p4],     make_float2(hv.x, hv.y), acc2a);
                acc2b = ffma2(wreg[2 * p4 + 1], make_float2(hv.z, hv.w), acc2b);
            }
#pragma unroll
            for (int q = 0; q < 7; ++q) {          // cols 96..123 (smem)
                float4 hv = h4[24 + q];
                float2 w01 = sh_w2[(2 * q) * 500 + r];
                float2 w23 = sh_w2[(2 * q + 1) * 500 + r];
                acc2a = ffma2(w01, make_float2(hv.x, hv.y), acc2a);
                acc2b = ffma2(w23, make_float2(hv.z, hv.w), acc2b);
            }
            float s = acc2a.x + acc2a.y + acc2b.x + acc2b.y
                    + sh_wl[r] * sh_h[124] + a_cur;
            sh_g[r] = s;
        }
        __syncthreads();
        if (r < HID) {
            float iv = sig_acc(sh_g[r]);
            float fv = sig_acc(sh_g[HID + r]);
            float gv = tanh_acc(sh_g[2 * HID + r]);
            float ov = sig_acc(sh_g[3 * HID + r]);
            creg = fv * creg + iv * gv;
            float hv = ov * tanh_acc(creg);
            sh_h[r] = hv;
            int row = dir ? (T_SEQ - 1 - t) : t;
            H[row * DHID + dir * HID + r] = hv;
        }
        __syncthreads();
        a_cur = a_next;
    }
}

// ---------------------------------------------------------------------------
// Pairwise MLP contraction:
//   out[j][i] = b2 + sum_k W2[k] * tanh(Pa[i][k] + Pbb[j][k])
// 32x32 output tile per CTA, 256 threads, 2x2 per thread, k chunked by 64.
// ---------------------------------------------------------------------------
__global__ void __launch_bounds__(256) pair_kernel(
    const float* __restrict__ Pa,   // [512][512]
    const float* __restrict__ Pb,   // [512][512] (b1 folded in)
    const float* __restrict__ W2,   // [512]
    const float* __restrict__ b2,   // [1]
    float* __restrict__ out)        // [512][512]  row=j, col=i
{
    __shared__ float pas[64][34];
    __shared__ float pbs[64][34];
    __shared__ float w2s[64];

    const int tid = threadIdx.x;
    const int ti = tid & 15;     // i pair
    const int tj = tid >> 4;     // j pair
    const int i0 = blockIdx.x * 32;
    const int j0 = blockIdx.y * 32;

    float acc00 = 0.f, acc01 = 0.f, acc10 = 0.f, acc11 = 0.f;

    for (int kc = 0; kc < MLPH; kc += 64) {
#pragma unroll
        for (int it = 0; it < 2; ++it) {
            int idx = tid + it * 256;
            int row = idx >> 4, q = idx & 15;
            float4 va = *(const float4*)&Pa[(long)(i0 + row) * MLPH + kc + 4 * q];
            pas[4 * q + 0][row] = va.x; pas[4 * q + 1][row] = va.y;
            pas[4 * q + 2][row] = va.z; pas[4 * q + 3][row] = va.w;
            float4 vb = *(const float4*)&Pb[(long)(j0 + row) * MLPH + kc + 4 * q];
            pbs[4 * q + 0][row] = vb.x; pbs[4 * q + 1][row] = vb.y;
            pbs[4 * q + 2][row] = vb.z; pbs[4 * q + 3][row] = vb.w;
        }
        if (tid < 16) {
            float4 w = *(const float4*)&W2[kc + 4 * tid];
            w2s[4 * tid + 0] = w.x; w2s[4 * tid + 1] = w.y;
            w2s[4 * tid + 2] = w.z; w2s[4 * tid + 3] = w.w;
        }
        __syncthreads();
#pragma unroll
        for (int kk = 0; kk < 64; ++kk) {
            float w = w2s[kk];
            float2 a = *(const float2*)&pas[kk][2 * ti];
            float2 b = *(const float2*)&pbs[kk][2 * tj];
            acc00 = fmaf(w, tanh_mufu(a.x + b.x), acc00);
            acc01 = fmaf(w, tanh_mufu(a.x + b.y), acc01);
            acc10 = fmaf(w, tanh_mufu(a.y + b.x), acc10);
            acc11 = fmaf(w, tanh_mufu(a.y + b.y), acc11);
        }
        __syncthreads();
    }

    float bb = b2[0];
    int i = i0 + 2 * ti;
    int j = j0 + 2 * tj;
    *(float2*)&out[(long)j * NN + i]       = make_float2(acc00 + bb, acc10 + bb);
    *(float2*)&out[(long)(j + 1) * NN + i] = make_float2(acc01 + bb, acc11 + bb);
}

// ---------------------------------------------------------------------------
// launch
// ---------------------------------------------------------------------------
extern "C" void kernel_launch(void* const* d_in, const int* in_sizes, int n_in,
                              void* d_out, int out_size)
{
    const float* x     = (const float*)d_in[0];   // (512,1,125)
    const float* Wih_f = (const float*)d_in[1];
    const float* Whh_f = (const float*)d_in[2];
    const float* bih_f = (const float*)d_in[3];
    const float* bhh_f = (const float*)d_in[4];
    const float* Wih_b = (const float*)d_in[5];
    const float* Whh_b = (const float*)d_in[6];
    const float* bih_b = (const float*)d_in[7];
    const float* bhh_b = (const float*)d_in[8];
    const float* W1    = (const float*)d_in[9];   // (512,500)
    const float* b1    = (const float*)d_in[10];  // (512)
    const float* W2    = (const float*)d_in[11];  // (1,512)
    const float* b2    = (const float*)d_in[12];  // (1)
    float* out = (float*)d_out;

    float *pA, *pH, *pP;
    cudaGetSymbolAddress((void**)&pA, g_A);
    cudaGetSymbolAddress((void**)&pH, g_H);
    cudaGetSymbolAddress((void**)&pP, g_P);
    float* pPa = pP;
    float* pPb = pP + NN * MLPH;

    cudaFuncSetAttribute(lstm_kernel,
                         cudaFuncAttributeMaxDynamicSharedMemorySize,
                         LSTM_SMEM_BYTES);

    dim3 blk(256);
    // A_f = x @ Wih_f^T + bih_f + bhh_f   (512 x 500)
    sgemm_tn<<<dim3(16, 16), blk>>>(x, 125, 0, 512, Wih_f, 125, GATES, 125,
                                    bih_f, bhh_f, pA, GATES);
    // A_b = rev(x) @ Wih_b^T + bih_b + bhh_b
    sgemm_tn<<<dim3(16, 16), blk>>>(x, 125, 1, 512, Wih_b, 125, GATES, 125,
                                    bih_b, bhh_b, pA + T_SEQ * GATES, GATES);
    // recurrence (fwd + bwd concurrently)
    lstm_kernel<<<2, 512, LSTM_SMEM_BYTES>>>(Whh_f, Whh_b, pA, pH);
    // Pa = H @ W1[:, :250]^T          (512 x 512)
    sgemm_tn<<<dim3(16, 16), blk>>>(pH, DHID, 0, 512, W1, 500, MLPH, DHID,
                                    nullptr, nullptr, pPa, MLPH);
    // Pb = H @ W1[:, 250:]^T + b1     (512 x 512)
    sgemm_tn<<<dim3(16, 16), blk>>>(pH, DHID, 0, 512, W1 + DHID, 500, MLPH, DHID,
                                    b1, nullptr, pPb, MLPH);
    // out[j][i] = b2 + sum_k W2[k] * tanh(Pa[i][k] + Pb[j][k])
    pair_kernel<<<dim3(16, 16), blk>>>(pPa, pPb, W2, b2, out);
}

// round 3
// speedup vs baseline: 1.0591x; 1.0591x over previous
#include <cuda_runtime.h>
#include <cuda_bf16.h>
#include <math.h>

#define T_SEQ   512
#define GATES   500
#define HID     125
#define DHID    250      // 2*HID
#define MLPH    512
#define NN      512

// Scratch (device globals; no allocation allowed)
__device__ float g_A[2 * T_SEQ * GATES];   // input projections (fwd/bwd)
__device__ float g_H[T_SEQ * DHID];        // concat hidden states
__device__ float g_P[2 * NN * MLPH];       // Pa, Pb(+b1)

// ---------------------------------------------------------------------------
// helpers
// ---------------------------------------------------------------------------
typedef unsigned long long ull;

// packed 2xfp32 FMA with no pack/unpack movs: operands live in 64-bit regs
__device__ __forceinline__ ull ffma2u(ull a, ull b, ull c) {
    ull d;
    asm("fma.rn.f32x2 %0, %1, %2, %3;" : "=l"(d) : "l"(a), "l"(b), "l"(c));
    return d;
}
__device__ __forceinline__ float2 u2f2(ull v) {
    float2 r;
    asm("mov.b64 {%0, %1}, %2;" : "=f"(r.x), "=f"(r.y) : "l"(v));
    return r;
}

__device__ __forceinline__ float tanh_mufu(float x) {
    float y;
    asm("tanh.approx.f32 %0, %1;" : "=f"(y) : "f"(x));
    return y;
}
__device__ __forceinline__ float sig_acc(float x) {
    return __fdividef(1.0f, 1.0f + __expf(-x));
}
__device__ __forceinline__ float tanh_acc(float x) {
    return 1.0f - __fdividef(2.0f, 1.0f + __expf(2.0f * x));
}

// ---------------------------------------------------------------------------
// Input projection, both directions in one launch.
//   A[dir][m][n] = sum_k x[rowA][k] * Wih_dir[n][k] + bih_dir[n] + bhh_dir[n]
//   rowA = dir ? 511-m : m
// grid (16,16,2), block 256. 32x32 tile, K=125.
// ---------------------------------------------------------------------------
__global__ void __launch_bounds__(256) proj_kernel(
    const float* __restrict__ x,
    const float* __restrict__ Wih_f, const float* __restrict__ bih_f,
    const float* __restrict__ bhh_f,
    const float* __restrict__ Wih_b, const float* __restrict__ bih_b,
    const float* __restrict__ bhh_b,
    float* __restrict__ Aout)
{
    const int dir = blockIdx.z;
    const float* __restrict__ W  = dir ? Wih_b : Wih_f;
    const float* __restrict__ bi = dir ? bih_b : bih_f;
    const float* __restrict__ bh = dir ? bhh_b : bhh_f;
    float* __restrict__ C = Aout + dir * (T_SEQ * GATES);

    __shared__ float As[16][34];
    __shared__ float Bs[16][34];

    const int tid = threadIdx.x;
    const int ti = tid & 15;
    const int tn = tid >> 4;
    const int m0 = blockIdx.x * 32;
    const int n0 = blockIdx.y * 32;

    float acc00 = 0.f, acc01 = 0.f, acc10 = 0.f, acc11 = 0.f;

    for (int kc = 0; kc < 125; kc += 16) {
#pragma unroll
        for (int it = 0; it < 2; ++it) {
            int idx = tid + it * 256;
            int mm = idx >> 4, kk = idx & 15;
            int k = kc + kk;
            int m = m0 + mm;
            int ra = dir ? (T_SEQ - 1 - m) : m;
            As[kk][mm] = (k < 125) ? x[(long)ra * 125 + k] : 0.f;
            int n = n0 + mm;
            Bs[kk][mm] = (n < GATES && k < 125) ? W[(long)n * 125 + k] : 0.f;
        }
        __syncthreads();
#pragma unroll
        for (int kk = 0; kk < 16; ++kk) {
            float2 av = *(const float2*)&As[kk][2 * ti];
            float2 bv = *(const float2*)&Bs[kk][2 * tn];
            acc00 = fmaf(av.x, bv.x, acc00);
            acc01 = fmaf(av.x, bv.y, acc01);
            acc10 = fmaf(av.y, bv.x, acc10);
            acc11 = fmaf(av.y, bv.y, acc11);
        }
        __syncthreads();
    }

    int m_ = m0 + 2 * ti;
    int n_ = n0 + 2 * tn;
    float b0 = 0.f, b1v = 0.f;
    if (n_ < GATES)     b0  = bi[n_] + bh[n_];
    if (n_ + 1 < GATES) b1v = bi[n_ + 1] + bh[n_ + 1];
    if (n_ < GATES) {
        C[(long)m_ * GATES + n_]       = acc00 + b0;
        C[(long)(m_ + 1) * GATES + n_] = acc10 + b0;
    }
    if (n_ + 1 < GATES) {
        C[(long)m_ * GATES + n_ + 1]       = acc01 + b1v;
        C[(long)(m_ + 1) * GATES + n_ + 1] = acc11 + b1v;
    }
}

// ---------------------------------------------------------------------------
// Pa / Pb in one launch. grid (16,16,2), block 256.
//   z=0: Pa[m][n] = sum_k H[m][k]     * W1[n][k]          (k in 0..249)
//   z=1: Pb[m][n] = sum_k H[m][k] * W1[n][250+k] + b1[n]
// ---------------------------------------------------------------------------
__global__ void __launch_bounds__(256) pab_kernel(
    const float* __restrict__ H,
    const float* __restrict__ W1,
    const float* __restrict__ b1,
    float* __restrict__ P)
{
    const int z = blockIdx.z;
    const float* __restrict__ B = W1 + (z ? DHID : 0);
    float* __restrict__ C = P + (long)z * NN * MLPH;

    __shared__ float As[16][34];
    __shared__ float Bs[16][34];

    const int tid = threadIdx.x;
    const int ti = tid & 15;
    const int tn = tid >> 4;
    const int m0 = blockIdx.x * 32;
    const int n0 = blockIdx.y * 32;

    float acc00 = 0.f, acc01 = 0.f, acc10 = 0.f, acc11 = 0.f;

    for (int kc = 0; kc < DHID; kc += 16) {
#pragma unroll
        for (int it = 0; it < 2; ++it) {
            int idx = tid + it * 256;
            int mm = idx >> 4, kk = idx & 15;
            int k = kc + kk;
            As[kk][mm] = (k < DHID) ? H[(long)(m0 + mm) * DHID + k] : 0.f;
            Bs[kk][mm] = (k < DHID) ? B[(long)(n0 + mm) * 500 + k] : 0.f;
        }
        __syncthreads();
#pragma unroll
        for (int kk = 0; kk < 16; ++kk) {
            float2 av = *(const float2*)&As[kk][2 * ti];
            float2 bv = *(const float2*)&Bs[kk][2 * tn];
            acc00 = fmaf(av.x, bv.x, acc00);
            acc01 = fmaf(av.x, bv.y, acc01);
            acc10 = fmaf(av.y, bv.x, acc10);
            acc11 = fmaf(av.y, bv.y, acc11);
        }
        __syncthreads();
    }

    int m_ = m0 + 2 * ti;
    int n_ = n0 + 2 * tn;
    float b0 = 0.f, b1v = 0.f;
    if (z) { b0 = b1[n_]; b1v = b1[n_ + 1]; }
    C[(long)m_ * MLPH + n_]           = acc00 + b0;
    C[(long)m_ * MLPH + n_ + 1]       = acc01 + b1v;
    C[(long)(m_ + 1) * MLPH + n_]     = acc10 + b0;
    C[(long)(m_ + 1) * MLPH + n_ + 1] = acc11 + b1v;
}

// ---------------------------------------------------------------------------
// LSTM recurrence. grid = 2 (dir), block = 512.
// Thread r < 500 owns gate row r: cols 0..95 in packed-ull registers,
// cols 96..123 as float4 in smem, col 124 scalar in smem.
// Smem layout (floats):
//   [0, 14000)      : float4 weights, [q in 0..6][row 0..499] (cols 96..123)
//   [14000, 14500)  : col-124 weights
//   [14500, 15012)  : g scratch
//   [15012, 15140)  : h (125 used, padded to 128; 16B aligned)
// ---------------------------------------------------------------------------
#define LSTM_SMEM_FLOATS (7 * 500 * 4 + 500 + 512 + 128)
#define LSTM_SMEM_BYTES  (LSTM_SMEM_FLOATS * 4)

__global__ void __launch_bounds__(512, 1) lstm_kernel(
    const float* __restrict__ Whh_f,
    const float* __restrict__ Whh_b,
    const float* __restrict__ A,     // [2][512][500]
    float* __restrict__ H)           // [512][250]
{
    extern __shared__ float smem[];
    float4* sh_w4 = (float4*)smem;             // 7*500 float4
    float*  sh_wl = smem + 7 * 500 * 4;        // 500
    float*  sh_g  = sh_wl + 500;               // 512
    float*  sh_h  = sh_g + 512;                // 128

    const int tid = threadIdx.x;
    const int dir = blockIdx.x;
    const float* __restrict__ Whh = dir ? Whh_b : Whh_f;
    const float* __restrict__ Ad = A + dir * (T_SEQ * GATES);
    const int r = tid;

    // stage shared weights: float4 for cols 96..123, scalar col 124
    for (int idx = tid; idx < 7 * 500; idx += 512) {
        int q = idx / 500, rr = idx - q * 500;
        const float* w = Whh + rr * 125 + 96 + 4 * q;
        sh_w4[q * 500 + rr] = make_float4(w[0], w[1], w[2], w[3]);
    }
    for (int idx = tid; idx < 500; idx += 512)
        sh_wl[idx] = Whh[idx * 125 + 124];

    // register weights: cols 0..95 packed as ull (2 fp32 each)
    ull wreg[48];
    if (r < GATES) {
        const ull* wr = (const ull*)(Whh + r * 125); // rows have odd length;
        // Whh + r*125 may be 4B-aligned only -> load scalars and pack.
        const float* wf = Whh + r * 125;
#pragma unroll
        for (int p = 0; p < 48; ++p) {
            float2 t = make_float2(wf[2 * p], wf[2 * p + 1]);
            wreg[p] = *(ull*)&t;
        }
        (void)wr;
    }

    if (tid < 128) sh_h[tid] = 0.f;
    float creg = 0.f;
    float a_cur = (r < GATES) ? Ad[r] : 0.f;
    __syncthreads();

    const ulonglong2* h2 = (const ulonglong2*)sh_h;   // 16B granules
    const ulonglong2* w2 = (const ulonglong2*)sh_w4;

    for (int t = 0; t < T_SEQ; ++t) {
        float a_next = (r < GATES && t < T_SEQ - 1) ? Ad[(t + 1) * GATES + r] : 0.f;
        if (r < GATES) {
            ull acc_a = 0ull, acc_b = 0ull;   // bit pattern of (0.f,0.f)
#pragma unroll
            for (int p = 0; p < 24; ++p) {    // cols 0..95 (registers)
                ulonglong2 hv = h2[p];
                acc_a = ffma2u(wreg[2 * p],     hv.x, acc_a);
                acc_b = ffma2u(wreg[2 * p + 1], hv.y, acc_b);
            }
#pragma unroll
            for (int q = 0; q < 7; ++q) {     // cols 96..123 (smem float4)
                ulonglong2 hv = h2[24 + q];
                ulonglong2 wv = w2[q * 500 + r];
                acc_a = ffma2u(wv.x, hv.x, acc_a);
                acc_b = ffma2u(wv.y, hv.y, acc_b);
            }
            float2 fa = u2f2(acc_a);
            float2 fb = u2f2(acc_b);
            sh_g[r] = fa.x + fa.y + fb.x + fb.y + sh_wl[r] * sh_h[124] + a_cur;
        }
        __syncthreads();
        if (r < HID) {
            float iv = sig_acc(sh_g[r]);
            float fv = sig_acc(sh_g[HID + r]);
            float gv = tanh_acc(sh_g[2 * HID + r]);
            float ov = sig_acc(sh_g[3 * HID + r]);
            creg = fv * creg + iv * gv;
            float hv = ov * tanh_acc(creg);
            sh_h[r] = hv;
            int row = dir ? (T_SEQ - 1 - t) : t;
            H[row * DHID + dir * HID + r] = hv;
        }
        __syncthreads();
        a_cur = a_next;
    }
}

// ---------------------------------------------------------------------------
// Pairwise MLP contraction:
//   out[j][i] = b2 + sum_k W2[k] * tanh(Pa[i][k] + Pb[j][k])
// 32x32 output tile per CTA, 256 threads, 2x2 per thread, k chunked by 64.
// ---------------------------------------------------------------------------
__global__ void __launch_bounds__(256) pair_kernel(
    const float* __restrict__ Pa,   // [512][512]
    const float* __restrict__ Pb,   // [512][512] (b1 folded in)
    const float* __restrict__ W2,   // [512]
    const float* __restrict__ b2,   // [1]
    float* __restrict__ out)        // [512][512]  row=j, col=i
{
    __shared__ float pas[64][34];
    __shared__ float pbs[64][34];
    __shared__ float w2s[64];

    const int tid = threadIdx.x;
    const int ti = tid & 15;     // i pair
    const int tj = tid >> 4;     // j pair
    const int i0 = blockIdx.x * 32;
    const int j0 = blockIdx.y * 32;

    float acc00 = 0.f, acc01 = 0.f, acc10 = 0.f, acc11 = 0.f;

    for (int kc = 0; kc < MLPH; kc += 64) {
#pragma unroll
        for (int it = 0; it < 2; ++it) {
            int idx = tid + it * 256;
            int row = idx >> 4, q = idx & 15;
            float4 va = *(const float4*)&Pa[(long)(i0 + row) * MLPH + kc + 4 * q];
            pas[4 * q + 0][row] = va.x; pas[4 * q + 1][row] = va.y;
            pas[4 * q + 2][row] = va.z; pas[4 * q + 3][row] = va.w;
            float4 vb = *(const float4*)&Pb[(long)(j0 + row) * MLPH + kc + 4 * q];
            pbs[4 * q + 0][row] = vb.x; pbs[4 * q + 1][row] = vb.y;
            pbs[4 * q + 2][row] = vb.z; pbs[4 * q + 3][row] = vb.w;
        }
        if (tid < 16) {
            float4 w = *(const float4*)&W2[kc + 4 * tid];
            w2s[4 * tid + 0] = w.x; w2s[4 * tid + 1] = w.y;
            w2s[4 * tid + 2] = w.z; w2s[4 * tid + 3] = w.w;
        }
        __syncthreads();
#pragma unroll
        for (int kk = 0; kk < 64; ++kk) {
            float w = w2s[kk];
            float2 a = *(const float2*)&pas[kk][2 * ti];
            float2 b = *(const float2*)&pbs[kk][2 * tj];
            acc00 = fmaf(w, tanh_mufu(a.x + b.x), acc00);
            acc01 = fmaf(w, tanh_mufu(a.x + b.y), acc01);
            acc10 = fmaf(w, tanh_mufu(a.y + b.x), acc10);
            acc11 = fmaf(w, tanh_mufu(a.y + b.y), acc11);
        }
        __syncthreads();
    }

    float bb = b2[0];
    int i = i0 + 2 * ti;
    int j = j0 + 2 * tj;
    *(float2*)&out[(long)j * NN + i]       = make_float2(acc00 + bb, acc10 + bb);
    *(float2*)&out[(long)(j + 1) * NN + i] = make_float2(acc01 + bb, acc11 + bb);
}

// ---------------------------------------------------------------------------
// launch
// ---------------------------------------------------------------------------
extern "C" void kernel_launch(void* const* d_in, const int* in_sizes, int n_in,
                              void* d_out, int out_size)
{
    const float* x     = (const float*)d_in[0];   // (512,1,125)
    const float* Wih_f = (const float*)d_in[1];
    const float* Whh_f = (const float*)d_in[2];
    const float* bih_f = (const float*)d_in[3];
    const float* bhh_f = (const float*)d_in[4];
    const float* Wih_b = (const float*)d_in[5];
    const float* Whh_b = (const float*)d_in[6];
    const float* bih_b = (const float*)d_in[7];
    const float* bhh_b = (const float*)d_in[8];
    const float* W1    = (const float*)d_in[9];   // (512,500)
    const float* b1    = (const float*)d_in[10];  // (512)
    const float* W2    = (const float*)d_in[11];  // (1,512)
    const float* b2    = (const float*)d_in[12];  // (1)
    float* out = (float*)d_out;

    float *pA, *pH, *pP;
    cudaGetSymbolAddress((void**)&pA, g_A);
    cudaGetSymbolAddress((void**)&pH, g_H);
    cudaGetSymbolAddress((void**)&pP, g_P);
    float* pPa = pP;
    float* pPb = pP + NN * MLPH;

    cudaFuncSetAttribute(lstm_kernel,
                         cudaFuncAttributeMaxDynamicSharedMemorySize,
                         LSTM_SMEM_BYTES);

    dim3 blk(256);
    // input projections, both directions in one launch
    proj_kernel<<<dim3(16, 16, 2), blk>>>(x, Wih_f, bih_f, bhh_f,
                                          Wih_b, bih_b, bhh_b, pA);
    // recurrence (fwd + bwd concurrently)
    lstm_kernel<<<2, 512, LSTM_SMEM_BYTES>>>(Whh_f, Whh_b, pA, pH);
    // Pa and Pb in one launch
    pab_kernel<<<dim3(16, 16, 2), blk>>>(pH, W1, b1, pP);
    // out[j][i] = b2 + sum_k W2[k] * tanh(Pa[i][k] + Pb[j][k])
    pair_kernel<<<dim3(16, 16), blk>>>(pPa, pPb, W2, b2, out);
}